// round 14
// baseline (speedup 1.0000x reference)
#include <cuda_runtime.h>
#include <cuda_fp16.h>
#include <math.h>
#include <stdint.h>

// Problem dims (fixed by the dataset)
#define NB    2048
#define CC    64
#define IND   512
#define HD1   256
#define HD2   256
#define HD3   128
#define DET1  128
#define DET2  64
#define MROWS (NB*CC)       // 131072
#define KDROP 44
#define TAU   0.95f

// smem row stride: 40 halves = 80 bytes (16B-aligned, ldmatrix conflict-free)
#define RS    40

// ---------------- scratch (no allocations allowed) ----------------
__device__ __half g_Hh [(size_t)MROWS*HD1];
__device__ __half g_Hl [(size_t)MROWS*HD1];
__device__ __half g_H2h[(size_t)MROWS*HD2];
__device__ __half g_H2l[(size_t)MROWS*HD2];
__device__ __half g_H3h[(size_t)MROWS*HD3];
__device__ __half g_H3l[(size_t)MROWS*HD3];
__device__ __half g_d1h[(size_t)MROWS*DET1];
__device__ __half g_d1l[(size_t)MROWS*DET1];
__device__ float  g_d2 [(size_t)MROWS*DET2];
__device__ float  g_scr[MROWS + NB];
__device__ __half g_wh[262144];
__device__ __half g_wl[262144];
#define OFF_W1 0
#define OFF_W2 131072
#define OFF_W3 196608
#define OFF_D1 229376
#define OFF_D2 245760
#define PREP_END 253952   // OFF_D2 + 128*64

// ---------------- PTX helpers ----------------
__device__ __forceinline__ uint32_t smem_u32(const void* p) {
    uint32_t a;
    asm("{ .reg .u64 t; cvta.to.shared.u64 t, %1; cvt.u32.u64 %0, t; }" : "=r"(a) : "l"(p));
    return a;
}
__device__ __forceinline__ void cp16(uint32_t dst, const void* src) {
    asm volatile("cp.async.cg.shared.global [%0], [%1], 16;" :: "r"(dst), "l"(src) : "memory");
}
__device__ __forceinline__ void cp_commit() {
    asm volatile("cp.async.commit_group;" ::: "memory");
}
__device__ __forceinline__ void ldm_x4(uint32_t* r, uint32_t addr) {
    asm volatile("ldmatrix.sync.aligned.m8n8.x4.shared.b16 {%0,%1,%2,%3}, [%4];"
        : "=r"(r[0]), "=r"(r[1]), "=r"(r[2]), "=r"(r[3]) : "r"(addr));
}
// fp32-accumulate (main hh term)
__device__ __forceinline__ void mma_f32acc(float* c, const uint32_t* a, const uint32_t* b) {
    asm volatile(
        "mma.sync.aligned.m16n8k16.row.col.f32.f16.f16.f32 "
        "{%0,%1,%2,%3}, {%4,%5,%6,%7}, {%8,%9}, {%0,%1,%2,%3};"
        : "+f"(c[0]), "+f"(c[1]), "+f"(c[2]), "+f"(c[3])
        : "r"(a[0]), "r"(a[1]), "r"(a[2]), "r"(a[3]), "r"(b[0]), "r"(b[1]));
}
// fp16-accumulate (low-order correction terms)
__device__ __forceinline__ void mma_f16acc(uint32_t* c, const uint32_t* a, const uint32_t* b) {
    asm volatile(
        "mma.sync.aligned.m16n8k16.row.col.f16.f16.f16.f16 "
        "{%0,%1}, {%2,%3,%4,%5}, {%6,%7}, {%0,%1};"
        : "+r"(c[0]), "+r"(c[1])
        : "r"(a[0]), "r"(a[1]), "r"(a[2]), "r"(a[3]), "r"(b[0]), "r"(b[1]));
}
__device__ __forceinline__ uint32_t pack2(__half a, __half b) {
    __half2 h2 = __halves2half2(a, b);
    return *reinterpret_cast<uint32_t*>(&h2);
}

// ---------------- prep: all 5 weights -> transposed hi/lo planes ----------
__global__ void prep_all(const float* __restrict__ W1, const float* __restrict__ W2,
                         const float* __restrict__ W3, const float* __restrict__ D1,
                         const float* __restrict__ D2,
                         __half* __restrict__ th, __half* __restrict__ tl)
{
    int i = blockIdx.x * 256 + threadIdx.x;
    const float* W; int base, K, N, off;
    if      (i < 131072)   { W = W1; base = 0;      K = 512; N = 256; off = OFF_W1; }
    else if (i < 196608)   { W = W2; base = 131072; K = 256; N = 256; off = OFF_W2; }
    else if (i < 229376)   { W = W3; base = 196608; K = 256; N = 128; off = OFF_W3; }
    else if (i < 245760)   { W = D1; base = 229376; K = 128; N = 128; off = OFF_D1; }
    else if (i < PREP_END) { W = D2; base = 245760; K = 128; N = 64;  off = OFF_D2; }
    else return;
    int j = i - base;
    int k = j / N, n = j % N;
    float x = W[j];
    __half h = __float2half_rn(x);
    __half l = __float2half_rn(x - __half2float(h));
    th[off + n * K + k] = h;
    tl[off + n * K + k] = l;
}

// ---- shared epilogue (merged fp32 value -> planes or fp32) ---------------
template<int ACT, int OUTF32>
__device__ __forceinline__ void epi_store(const float* a4, int row, int col, int Ntot,
    const float* __restrict__ bias, __half* __restrict__ Ch,
    __half* __restrict__ Cl, float* __restrict__ Cf)
{
    const float b0 = bias[col], b1 = bias[col + 1];
    float v0 = a4[0] + b0, v1 = a4[1] + b1;
    float v2 = a4[2] + b0, v3 = a4[3] + b1;
    if (ACT == 1) {
        v0 = fmaxf(v0, 0.0f); v1 = fmaxf(v1, 0.0f);
        v2 = fmaxf(v2, 0.0f); v3 = fmaxf(v3, 0.0f);
    } else if (ACT == 2) {
        v0 = 1.0f / (1.0f + expf(-v0)); v1 = 1.0f / (1.0f + expf(-v1));
        v2 = 1.0f / (1.0f + expf(-v2)); v3 = 1.0f / (1.0f + expf(-v3));
    }
    if (OUTF32) {
        *reinterpret_cast<float2*>(Cf + (size_t)row * Ntot + col) = make_float2(v0, v1);
        *reinterpret_cast<float2*>(Cf + (size_t)(row + 8) * Ntot + col) = make_float2(v2, v3);
    } else {
        __half h0 = __float2half_rn(v0), h1 = __float2half_rn(v1);
        __half h2 = __float2half_rn(v2), h3 = __float2half_rn(v3);
        __half l0 = __float2half_rn(v0 - __half2float(h0));
        __half l1 = __float2half_rn(v1 - __half2float(h1));
        __half l2 = __float2half_rn(v2 - __half2float(h2));
        __half l3 = __float2half_rn(v3 - __half2float(h3));
        *reinterpret_cast<__half2*>(Ch + (size_t)row * Ntot + col) = __halves2half2(h0, h1);
        *reinterpret_cast<__half2*>(Cl + (size_t)row * Ntot + col) = __halves2half2(l0, l1);
        *reinterpret_cast<__half2*>(Ch + (size_t)(row + 8) * Ntot + col) = __halves2half2(h2, h3);
        *reinterpret_cast<__half2*>(Cl + (size_t)(row + 8) * Ntot + col) = __halves2half2(l2, l3);
    }
}

// ---------------- plane-input GEMM (layers 2-5) ---------------------------
// CTA: 128(M) x BN(N), TH = BN*2 threads, warps 2(m) x BN/32(n),
// warp tile 64 x 32. hh -> fp32 acc, (ah*bl + al*bh) -> shared fp16 acc.
// 3-stage cp.async ring.
template<int BN, int ACT, int OUTF32>
__global__ void __launch_bounds__(BN*2, (BN == 64) ? 2 : 1)
gemm_p(const __half* __restrict__ Agh, const __half* __restrict__ Agl,
       const __half* __restrict__ Bgh, const __half* __restrict__ Bgl,
       const float* __restrict__ bias,
       __half* __restrict__ Ch, __half* __restrict__ Cl,
       float* __restrict__ Cf, int K, int Ntot)
{
    constexpr int TH   = BN * 2;
    constexpr int WC   = BN / 32;          // n-warps
    constexpr int NT   = 4;                // n8 tiles per warp (32 cols)
    constexpr int NP   = 2;
    constexpr int AB   = 128 * RS * 2;     // bytes per A plane (hi or lo)
    constexpr int BB   = BN * RS * 2;
    constexpr int BUFB = 2 * AB + 2 * BB;
    extern __shared__ char smem[];
    const uint32_t sb = smem_u32(smem);

    const int tid = threadIdx.x;
    const int wid = tid >> 5, lane = tid & 31;
    const int wm  = wid / WC, wn = wid % WC;
    const int g   = lane >> 2, tig = lane & 3;
    const int n0  = blockIdx.x * BN;
    const int m0  = blockIdx.y * 128;

    const uint32_t aoff = (uint32_t)((lane & 15) * RS + ((lane >> 4) << 3)) * 2;
    const uint32_t boff = (uint32_t)(((lane & 7) + ((lane >> 4) & 1) * 8) * RS
                                     + (((lane >> 3) & 1) << 3)) * 2;

    float    acc32[4][NT][4];
    uint32_t acc16[4][NT][2];
    #pragma unroll
    for (int i = 0; i < 4; i++)
        #pragma unroll
        for (int j = 0; j < NT; j++) {
            #pragma unroll
            for (int q = 0; q < 4; q++) acc32[i][j][q] = 0.0f;
            acc16[i][j][0] = 0u; acc16[i][j][1] = 0u;
        }

    const int NC = K >> 5;

    auto cp_chunk = [&](int c, int b) {
        const int k0 = c << 5;
        const uint32_t a_h = sb + b * BUFB;
        const uint32_t a_l = a_h + AB;
        const uint32_t b_h = a_h + 2 * AB;
        const uint32_t b_l = b_h + BB;
        #pragma unroll
        for (int it = 0; it < 512 / TH; ++it) {       // A: 128 rows x 4 kc
            int idx = tid + it * TH;
            int r = idx >> 2, kc = idx & 3;
            size_t so = (size_t)(m0 + r) * K + k0 + kc * 8;
            uint32_t doff = (uint32_t)(r * RS + kc * 8) * 2;
            cp16(a_h + doff, Agh + so);
            cp16(a_l + doff, Agl + so);
        }
        #pragma unroll
        for (int it = 0; it < BN * 4 / TH; ++it) {    // B: BN rows x 4 kc
            int idx = tid + it * TH;
            int r = idx >> 2, kc = idx & 3;
            size_t so = (size_t)(n0 + r) * K + k0 + kc * 8;
            uint32_t doff = (uint32_t)(r * RS + kc * 8) * 2;
            cp16(b_h + doff, Bgh + so);
            cp16(b_l + doff, Bgl + so);
        }
        cp_commit();
    };

    cp_chunk(0, 0);
    cp_chunk(1, 1);
    for (int c = 0; c < NC; ++c) {
        const int b = c % 3;
        if (c + 1 < NC) asm volatile("cp.async.wait_group 1;" ::: "memory");
        else            asm volatile("cp.async.wait_group 0;" ::: "memory");
        __syncthreads();
        if (c + 2 < NC) cp_chunk(c + 2, (c + 2) % 3);

        const uint32_t base = sb + b * BUFB;
        const uint32_t sAh = base, sAl = base + AB;
        const uint32_t sBh = base + 2 * AB, sBl = sBh + BB;
        #pragma unroll
        for (int ks = 0; ks < 2; ++ks) {
            const uint32_t kb = (uint32_t)ks * 32;
            uint32_t ah[4][4], al[4][4], bh[NP][4], bl[NP][4];
            #pragma unroll
            for (int mt = 0; mt < 4; ++mt) {
                const uint32_t ro = (uint32_t)(wm * 64 + mt * 16) * (RS * 2);
                ldm_x4(ah[mt], sAh + ro + kb + aoff);
                ldm_x4(al[mt], sAl + ro + kb + aoff);
            }
            #pragma unroll
            for (int p = 0; p < NP; ++p) {
                const uint32_t no = (uint32_t)(wn * 32 + p * 16) * (RS * 2);
                ldm_x4(bh[p], sBh + no + kb + boff);
                ldm_x4(bl[p], sBl + no + kb + boff);
            }
            // main term: fp32 accumulate
            #pragma unroll
            for (int mt = 0; mt < 4; ++mt)
                #pragma unroll
                for (int p = 0; p < NP; ++p) {
                    mma_f32acc(acc32[mt][2*p],   ah[mt], &bh[p][0]);
                    mma_f32acc(acc32[mt][2*p+1], ah[mt], &bh[p][2]);
                }
            // low-order terms: fp16 accumulate (shared accumulator)
            #pragma unroll
            for (int mt = 0; mt < 4; ++mt)
                #pragma unroll
                for (int p = 0; p < NP; ++p) {
                    mma_f16acc(acc16[mt][2*p],   ah[mt], &bl[p][0]);
                    mma_f16acc(acc16[mt][2*p+1], ah[mt], &bl[p][2]);
                }
            #pragma unroll
            for (int mt = 0; mt < 4; ++mt)
                #pragma unroll
                for (int p = 0; p < NP; ++p) {
                    mma_f16acc(acc16[mt][2*p],   al[mt], &bh[p][0]);
                    mma_f16acc(acc16[mt][2*p+1], al[mt], &bh[p][2]);
                }
        }
        __syncthreads();
    }

    #pragma unroll
    for (int mt = 0; mt < 4; ++mt) {
        const int row = m0 + wm * 64 + mt * 16 + g;
        #pragma unroll
        for (int nt = 0; nt < NT; ++nt) {
            const int col = n0 + wn * 32 + nt * 8 + tig * 2;
            __half2 p0 = *reinterpret_cast<__half2*>(&acc16[mt][nt][0]);
            __half2 p1 = *reinterpret_cast<__half2*>(&acc16[mt][nt][1]);
            float a4[4];
            a4[0] = acc32[mt][nt][0] + __low2float(p0);
            a4[1] = acc32[mt][nt][1] + __high2float(p0);
            a4[2] = acc32[mt][nt][2] + __low2float(p1);
            a4[3] = acc32[mt][nt][3] + __high2float(p1);
            epi_store<ACT, OUTF32>(a4, row, col, Ntot, bias, Ch, Cl, Cf);
        }
    }
}

// ---------------- fp32-input GEMM (layer 1) -------------------------------
// CTA 128 x 128, 256 threads, warps 2x4, warp tile 64x32. 2-stage.
__global__ void __launch_bounds__(256, 1)
gemm_x(const float* __restrict__ A, const __half* __restrict__ Bgh,
       const __half* __restrict__ Bgl, const float* __restrict__ bias,
       __half* __restrict__ Ch, __half* __restrict__ Cl, int K, int Ntot)
{
    constexpr int BN   = 128;
    constexpr int NT   = 4;
    constexpr int NP   = 2;
    constexpr int AB   = 128 * RS * 2;
    constexpr int BB   = BN * RS * 2;
    constexpr int BUFB = 2 * AB + 2 * BB;
    extern __shared__ char smem[];
    const uint32_t sb = smem_u32(smem);

    const int tid = threadIdx.x;
    const int wid = tid >> 5, lane = tid & 31;
    const int wm  = wid >> 2, wn = wid & 3;
    const int g   = lane >> 2, tig = lane & 3;
    const int n0  = blockIdx.x * BN;
    const int m0  = blockIdx.y * 128;

    const uint32_t aoff = (uint32_t)((lane & 15) * RS + ((lane >> 4) << 3)) * 2;
    const uint32_t boff = (uint32_t)(((lane & 7) + ((lane >> 4) & 1) * 8) * RS
                                     + (((lane >> 3) & 1) << 3)) * 2;

    float    acc32[4][NT][4];
    uint32_t acc16[4][NT][2];
    #pragma unroll
    for (int i = 0; i < 4; i++)
        #pragma unroll
        for (int j = 0; j < NT; j++) {
            #pragma unroll
            for (int q = 0; q < 4; q++) acc32[i][j][q] = 0.0f;
            acc16[i][j][0] = 0u; acc16[i][j][1] = 0u;
        }

    const int NC = K >> 5;
    float4 rA[4];

    auto cpB = [&](int c, int b) {
        const int k0 = c << 5;
        uint32_t dh = sb + b * BUFB + 2 * AB;
        uint32_t dl = dh + BB;
        #pragma unroll
        for (int it = 0; it < 2; ++it) {
            int idx = tid + it * 256;
            int n = idx >> 2, kc = idx & 3;
            size_t so = (size_t)(n0 + n) * K + k0 + kc * 8;
            uint32_t doff = (uint32_t)(n * RS + kc * 8) * 2;
            cp16(dh + doff, Bgh + so);
            cp16(dl + doff, Bgl + so);
        }
        cp_commit();
    };

    // A chunk: 128 rows x 8 float4 groups = 1024 items -> 4 per thread
    #pragma unroll
    for (int it = 0; it < 4; ++it) {
        int idx = tid + it * 256;
        rA[it] = *reinterpret_cast<const float4*>(
            A + (size_t)(m0 + (idx >> 3)) * K + (idx & 7) * 4);
    }
    cpB(0, 0);

    for (int c = 0; c < NC; ++c) {
        const int b = c & 1;
        if (c + 1 < NC) cpB(c + 1, b ^ 1);
        {
            __half* Ah = reinterpret_cast<__half*>(smem + b * BUFB);
            __half* Al = reinterpret_cast<__half*>(smem + b * BUFB + AB);
            #pragma unroll
            for (int it = 0; it < 4; ++it) {
                int idx = tid + it * 256;
                const int row = idx >> 3, kq = idx & 7;
                const float4 a = rA[it];
                __half hx = __float2half_rn(a.x), hy = __float2half_rn(a.y);
                __half hz = __float2half_rn(a.z), hw = __float2half_rn(a.w);
                __half lx = __float2half_rn(a.x - __half2float(hx));
                __half ly = __float2half_rn(a.y - __half2float(hy));
                __half lz = __float2half_rn(a.z - __half2float(hz));
                __half lw = __float2half_rn(a.w - __half2float(hw));
                *reinterpret_cast<uint2*>(Ah + row * RS + kq * 4) =
                    make_uint2(pack2(hx, hy), pack2(hz, hw));
                *reinterpret_cast<uint2*>(Al + row * RS + kq * 4) =
                    make_uint2(pack2(lx, ly), pack2(lz, lw));
            }
        }
        if (c + 1 < NC) {
            const float* An = A + (size_t)m0 * K + ((c + 1) << 5);
            #pragma unroll
            for (int it = 0; it < 4; ++it) {
                int idx = tid + it * 256;
                rA[it] = *reinterpret_cast<const float4*>(
                    An + (size_t)(idx >> 3) * K + (idx & 7) * 4);
            }
        }
        if (c + 1 < NC) asm volatile("cp.async.wait_group 1;" ::: "memory");
        else            asm volatile("cp.async.wait_group 0;" ::: "memory");
        __syncthreads();

        const uint32_t base = sb + b * BUFB;
        const uint32_t sAh = base, sAl = base + AB;
        const uint32_t sBh = base + 2 * AB, sBl = sBh + BB;
        #pragma unroll
        for (int ks = 0; ks < 2; ++ks) {
            const uint32_t kb = (uint32_t)ks * 32;
            uint32_t ah[4][4], al[4][4], bh[NP][4], bl[NP][4];
            #pragma unroll
            for (int mt = 0; mt < 4; ++mt) {
                const uint32_t ro = (uint32_t)(wm * 64 + mt * 16) * (RS * 2);
                ldm_x4(ah[mt], sAh + ro + kb + aoff);
                ldm_x4(al[mt], sAl + ro + kb + aoff);
            }
            #pragma unroll
            for (int p = 0; p < NP; ++p) {
                const uint32_t no = (uint32_t)(wn * 32 + p * 16) * (RS * 2);
                ldm_x4(bh[p], sBh + no + kb + boff);
                ldm_x4(bl[p], sBl + no + kb + boff);
            }
            #pragma unroll
            for (int mt = 0; mt < 4; ++mt)
                #pragma unroll
                for (int p = 0; p < NP; ++p) {
                    mma_f32acc(acc32[mt][2*p],   ah[mt], &bh[p][0]);
                    mma_f32acc(acc32[mt][2*p+1], ah[mt], &bh[p][2]);
                }
            #pragma unroll
            for (int mt = 0; mt < 4; ++mt)
                #pragma unroll
                for (int p = 0; p < NP; ++p) {
                    mma_f16acc(acc16[mt][2*p],   ah[mt], &bl[p][0]);
                    mma_f16acc(acc16[mt][2*p+1], ah[mt], &bl[p][2]);
                }
            #pragma unroll
            for (int mt = 0; mt < 4; ++mt)
                #pragma unroll
                for (int p = 0; p < NP; ++p) {
                    mma_f16acc(acc16[mt][2*p],   al[mt], &bh[p][0]);
                    mma_f16acc(acc16[mt][2*p+1], al[mt], &bh[p][2]);
                }
        }
        __syncthreads();
    }

    #pragma unroll
    for (int mt = 0; mt < 4; ++mt) {
        const int row = m0 + wm * 64 + mt * 16 + g;
        #pragma unroll
        for (int nt = 0; nt < NT; ++nt) {
            const int col = n0 + wn * 32 + nt * 8 + tig * 2;
            __half2 p0 = *reinterpret_cast<__half2*>(&acc16[mt][nt][0]);
            __half2 p1 = *reinterpret_cast<__half2*>(&acc16[mt][nt][1]);
            float a4[4];
            a4[0] = acc32[mt][nt][0] + __low2float(p0);
            a4[1] = acc32[mt][nt][1] + __high2float(p0);
            a4[2] = acc32[mt][nt][2] + __low2float(p1);
            a4[3] = acc32[mt][nt][3] + __high2float(p1);
            epi_store<1, 0>(a4, row, col, Ntot, bias, Ch, Cl, nullptr);
        }
    }
}

// ---------------- per-bag finish ----------------
__global__ void __launch_bounds__(128)
finish_kernel(const float* __restrict__ d2v, const float* __restrict__ D3,
              const float* __restrict__ db3, const float* __restrict__ m,
              const float* __restrict__ u,
              const __half* __restrict__ H3h, const __half* __restrict__ H3l,
              const float* __restrict__ E,   const float* __restrict__ eb,
              float* __restrict__ outw, float* __restrict__ outv)
{
    const int n   = blockIdx.x;
    const int tid = threadIdx.x;

    __shared__ float s_d2[CC][DET2 + 1];
    __shared__ float s_D3[DET2];
    __shared__ float s_z[CC];
    __shared__ float s_w2[CC];
    __shared__ float s_w[CC];
    __shared__ int   s_keep[CC];
    __shared__ float s_red[128];
    __shared__ float s_mx, s_sum;

    const float* d2b = d2v + (size_t)n * CC * DET2;
    for (int idx = tid; idx < CC * DET2; idx += 128)
        s_d2[idx >> 6][idx & 63] = d2b[idx];
    if (tid < DET2) s_D3[tid] = D3[tid];
    __syncthreads();

    if (tid < CC) {
        const int c = tid;
        float dd = db3[0];
        #pragma unroll
        for (int j = 0; j < DET2; j++) dd = fmaf(s_d2[c][j], s_D3[j], dd);
        float logit = m[(size_t)n * CC + c] * dd;
        float uu = u[(size_t)n * CC + c];
        float gn = -logf(-logf(uu));
        s_z[c] = (logit + gn) / TAU;
    }
    __syncthreads();

    if (tid == 0) {
        float mx = s_z[0];
        for (int c = 1; c < CC; c++) mx = fmaxf(mx, s_z[c]);
        s_mx = mx;
    }
    __syncthreads();
    if (tid < CC) s_w2[tid] = expf(s_z[tid] - s_mx);
    __syncthreads();
    if (tid == 0) {
        float s = 0.0f;
        for (int c = 0; c < CC; c++) s += s_w2[c];
        s_sum = s;
    }
    __syncthreads();
    if (tid < CC) s_w2[tid] = s_w2[tid] / s_sum;
    __syncthreads();

    if (tid < CC) {
        const int c = tid;
        const float v = s_w2[c];
        int rank = 0;
        for (int c2 = 0; c2 < CC; c2++) {
            float v2 = s_w2[c2];
            rank += (v2 < v) || (v2 == v && c2 < c);
        }
        s_keep[c] = (rank >= KDROP);
    }
    __syncthreads();

    if (tid == 0) {
        float mx = -INFINITY;
        for (int c = 0; c < CC; c++)
            if (s_keep[c]) mx = fmaxf(mx, s_w2[c]);
        s_mx = mx;
    }
    __syncthreads();
    if (tid < CC) s_red[tid] = s_keep[tid] ? expf(s_w2[tid] - s_mx) : 0.0f;
    __syncthreads();
    if (tid == 0) {
        float s = 0.0f;
        for (int c = 0; c < CC; c++) s += s_red[c];
        s_sum = s;
    }
    __syncthreads();
    if (tid < CC) {
        float wv = s_keep[tid] ? s_red[tid] / s_sum : 0.0f;
        s_w[tid] = wv;
        outw[(size_t)n * CC + tid] = wv;
    }
    __syncthreads();

    {
        const __half* hb = H3h + (size_t)n * CC * HD3;
        const __half* lb = H3l + (size_t)n * CC * HD3;
        float a = 0.0f;
        #pragma unroll 8
        for (int c = 0; c < CC; c++) {
            float h3 = __half2float(hb[(size_t)c * HD3 + tid]) +
                       __half2float(lb[(size_t)c * HD3 + tid]);
            a = fmaf(s_w[c], h3, a);
        }
        s_red[tid] = a * E[tid];
    }
    __syncthreads();
    for (int off = 64; off > 0; off >>= 1) {
        if (tid < off) s_red[tid] += s_red[tid + off];
        __syncthreads();
    }
    if (tid == 0) outv[n] = s_red[0] + eb[0];
}

// ---------------- launch ----------------
static inline int smemP(int BN) {                 // 3-stage ring
    return 3 * (2 * 128 * RS * 2 + 2 * BN * RS * 2);
}
static inline int smemX() {                       // 2-stage
    return 2 * (2 * 128 * RS * 2 + 2 * 128 * RS * 2);
}

extern "C" void kernel_launch(void* const* d_in, const int* in_sizes, int n_in,
                              void* d_out, int out_size)
{
    const float* x   = (const float*)d_in[0];
    const float* m   = (const float*)d_in[1];
    const float* u   = (const float*)d_in[2];
    const float* W1  = (const float*)d_in[3];
    const float* b1  = (const float*)d_in[4];
    const float* W2  = (const float*)d_in[5];
    const float* b2  = (const float*)d_in[6];
    const float* W3  = (const float*)d_in[7];
    const float* b3  = (const float*)d_in[8];
    const float* D1  = (const float*)d_in[9];
    const float* db1 = (const float*)d_in[10];
    const float* D2  = (const float*)d_in[11];
    const float* db2 = (const float*)d_in[12];
    const float* D3  = (const float*)d_in[13];
    const float* db3 = (const float*)d_in[14];
    const float* E   = (const float*)d_in[15];
    const float* eb  = (const float*)d_in[16];

    static __half *pHh = nullptr, *pHl, *pH2h, *pH2l, *pH3h, *pH3l, *pd1h, *pd1l, *pwh, *pwl;
    static float  *pd2, *pscr;
    if (!pHh) {
        cudaGetSymbolAddress((void**)&pHh,  g_Hh);
        cudaGetSymbolAddress((void**)&pHl,  g_Hl);
        cudaGetSymbolAddress((void**)&pH2h, g_H2h);
        cudaGetSymbolAddress((void**)&pH2l, g_H2l);
        cudaGetSymbolAddress((void**)&pH3h, g_H3h);
        cudaGetSymbolAddress((void**)&pH3l, g_H3l);
        cudaGetSymbolAddress((void**)&pd1h, g_d1h);
        cudaGetSymbolAddress((void**)&pd1l, g_d1l);
        cudaGetSymbolAddress((void**)&pd2,  g_d2);
        cudaGetSymbolAddress((void**)&pscr, g_scr);
        cudaGetSymbolAddress((void**)&pwh,  g_wh);
        cudaGetSymbolAddress((void**)&pwl,  g_wl);
        cudaFuncSetAttribute(gemm_x, cudaFuncAttributeMaxDynamicSharedMemorySize, smemX());
        cudaFuncSetAttribute(gemm_p<128,1,0>, cudaFuncAttributeMaxDynamicSharedMemorySize, smemP(128));
        cudaFuncSetAttribute(gemm_p<128,2,0>, cudaFuncAttributeMaxDynamicSharedMemorySize, smemP(128));
        cudaFuncSetAttribute(gemm_p<64,2,1>,  cudaFuncAttributeMaxDynamicSharedMemorySize, smemP(64));
    }

    float* outw = (float*)d_out;
    float* outv;
    if (out_size >= MROWS + NB)      { outv = outw + MROWS; }
    else if (out_size == MROWS)      { outv = pscr; }
    else                             { outv = (float*)d_out; outw = pscr; }

    prep_all<<<PREP_END/256, 256>>>(W1, W2, W3, D1, D2, pwh, pwl);

    const int G = MROWS / 128;   // 1024 m-blocks
    // layer 1: x fp32, K=512, N=256 (2 n-blocks), relu -> H planes
    gemm_x<<<dim3(2, G), 256, smemX()>>>(
        x, pwh + OFF_W1, pwl + OFF_W1, b1, pHh, pHl, IND, HD1);
    // layer 2: K=256, N=256 (2 n-blocks), relu -> H2 planes
    gemm_p<128,1,0><<<dim3(2, G), 256, smemP(128)>>>(
        pHh, pHl, pwh + OFF_W2, pwl + OFF_W2, b2, pH2h, pH2l, nullptr, HD1, HD2);
    // layer 3: K=256, N=128, relu -> H3 planes
    gemm_p<128,1,0><<<dim3(1, G), 256, smemP(128)>>>(
        pH2h, pH2l, pwh + OFF_W3, pwl + OFF_W3, b3, pH3h, pH3l, nullptr, HD2, HD3);
    // detector 1: K=128, N=128, sigmoid -> d1 planes
    gemm_p<128,2,0><<<dim3(1, G), 256, smemP(128)>>>(
        pH3h, pH3l, pwh + OFF_D1, pwl + OFF_D1, db1, pd1h, pd1l, nullptr, HD3, DET1);
    // detector 2: K=128, N=64, sigmoid -> d2 fp32
    gemm_p<64,2,1><<<dim3(1, G), 128, smemP(64)>>>(
        pd1h, pd1l, pwh + OFF_D2, pwl + OFF_D2, db2, nullptr, nullptr, pd2, DET1, DET2);

    finish_kernel<<<NB, 128>>>(pd2, D3, db3, m, u, pH3h, pH3l, E, eb, outw, outv);
}

// round 15
// speedup vs baseline: 1.1960x; 1.1960x over previous
#include <cuda_runtime.h>
#include <cuda_fp16.h>
#include <math.h>
#include <stdint.h>

// Problem dims (fixed by the dataset)
#define NB    2048
#define CC    64
#define IND   512
#define HD1   256
#define HD2   256
#define HD3   128
#define DET1  128
#define DET2  64
#define MROWS (NB*CC)       // 131072
#define KDROP 44
#define TAU   0.95f

// smem row stride: 40 halves = 80 bytes (16B-aligned, ldmatrix conflict-free)
#define RS    40

// ---------------- scratch (no allocations allowed) ----------------
__device__ __half g_Hh [(size_t)MROWS*HD1];
__device__ __half g_Hl [(size_t)MROWS*HD1];
__device__ __half g_H2h[(size_t)MROWS*HD2];
__device__ __half g_H2l[(size_t)MROWS*HD2];
__device__ __half g_H3h[(size_t)MROWS*HD3];
__device__ __half g_H3l[(size_t)MROWS*HD3];
__device__ float  g_d2 [(size_t)MROWS*DET2];
__device__ float  g_scr[MROWS + NB];
__device__ __half g_wh[262144];
__device__ __half g_wl[262144];
#define OFF_W1 0
#define OFF_W2 131072
#define OFF_W3 196608
#define OFF_D1 229376
#define OFF_D2 245760
#define PREP_END 253952   // OFF_D2 + 128*64

// ---------------- PTX helpers ----------------
__device__ __forceinline__ uint32_t smem_u32(const void* p) {
    uint32_t a;
    asm("{ .reg .u64 t; cvta.to.shared.u64 t, %1; cvt.u32.u64 %0, t; }" : "=r"(a) : "l"(p));
    return a;
}
__device__ __forceinline__ void cp16(uint32_t dst, const void* src) {
    asm volatile("cp.async.cg.shared.global [%0], [%1], 16;" :: "r"(dst), "l"(src) : "memory");
}
__device__ __forceinline__ void cp_commit() {
    asm volatile("cp.async.commit_group;" ::: "memory");
}
__device__ __forceinline__ void ldm_x4(uint32_t* r, uint32_t addr) {
    asm volatile("ldmatrix.sync.aligned.m8n8.x4.shared.b16 {%0,%1,%2,%3}, [%4];"
        : "=r"(r[0]), "=r"(r[1]), "=r"(r[2]), "=r"(r[3]) : "r"(addr));
}
__device__ __forceinline__ void mma_f16(float* c, const uint32_t* a, const uint32_t* b) {
    asm volatile(
        "mma.sync.aligned.m16n8k16.row.col.f32.f16.f16.f32 "
        "{%0,%1,%2,%3}, {%4,%5,%6,%7}, {%8,%9}, {%0,%1,%2,%3};"
        : "+f"(c[0]), "+f"(c[1]), "+f"(c[2]), "+f"(c[3])
        : "r"(a[0]), "r"(a[1]), "r"(a[2]), "r"(a[3]), "r"(b[0]), "r"(b[1]));
}
__device__ __forceinline__ uint32_t pack2(__half a, __half b) {
    __half2 h2 = __halves2half2(a, b);
    return *reinterpret_cast<uint32_t*>(&h2);
}

// ---------------- prep: all 5 weights -> transposed hi/lo planes ----------
__global__ void prep_all(const float* __restrict__ W1, const float* __restrict__ W2,
                         const float* __restrict__ W3, const float* __restrict__ D1,
                         const float* __restrict__ D2,
                         __half* __restrict__ th, __half* __restrict__ tl)
{
    int i = blockIdx.x * 256 + threadIdx.x;
    const float* W; int base, K, N, off;
    if      (i < 131072)   { W = W1; base = 0;      K = 512; N = 256; off = OFF_W1; }
    else if (i < 196608)   { W = W2; base = 131072; K = 256; N = 256; off = OFF_W2; }
    else if (i < 229376)   { W = W3; base = 196608; K = 256; N = 128; off = OFF_W3; }
    else if (i < 245760)   { W = D1; base = 229376; K = 128; N = 128; off = OFF_D1; }
    else if (i < PREP_END) { W = D2; base = 245760; K = 128; N = 64;  off = OFF_D2; }
    else return;
    int j = i - base;
    int k = j / N, n = j % N;
    float x = W[j];
    __half h = __float2half_rn(x);
    __half l = __float2half_rn(x - __half2float(h));
    th[off + n * K + k] = h;
    tl[off + n * K + k] = l;
}

// ---- shared epilogue ------------------------------------------------------
template<int ACT, int OUTF32>
__device__ __forceinline__ void epi_store(const float* a4, int row, int col, int Ntot,
    const float* __restrict__ bias, __half* __restrict__ Ch,
    __half* __restrict__ Cl, float* __restrict__ Cf)
{
    const float b0 = bias[col], b1 = bias[col + 1];
    float v0 = a4[0] + b0, v1 = a4[1] + b1;
    float v2 = a4[2] + b0, v3 = a4[3] + b1;
    if (ACT == 1) {
        v0 = fmaxf(v0, 0.0f); v1 = fmaxf(v1, 0.0f);
        v2 = fmaxf(v2, 0.0f); v3 = fmaxf(v3, 0.0f);
    } else if (ACT == 2) {
        v0 = 1.0f / (1.0f + expf(-v0)); v1 = 1.0f / (1.0f + expf(-v1));
        v2 = 1.0f / (1.0f + expf(-v2)); v3 = 1.0f / (1.0f + expf(-v3));
    }
    if (OUTF32) {
        *reinterpret_cast<float2*>(Cf + (size_t)row * Ntot + col) = make_float2(v0, v1);
        *reinterpret_cast<float2*>(Cf + (size_t)(row + 8) * Ntot + col) = make_float2(v2, v3);
    } else {
        __half h0 = __float2half_rn(v0), h1 = __float2half_rn(v1);
        __half h2 = __float2half_rn(v2), h3 = __float2half_rn(v3);
        __half l0 = __float2half_rn(v0 - __half2float(h0));
        __half l1 = __float2half_rn(v1 - __half2float(h1));
        __half l2 = __float2half_rn(v2 - __half2float(h2));
        __half l3 = __float2half_rn(v3 - __half2float(h3));
        *reinterpret_cast<__half2*>(Ch + (size_t)row * Ntot + col) = __halves2half2(h0, h1);
        *reinterpret_cast<__half2*>(Cl + (size_t)row * Ntot + col) = __halves2half2(l0, l1);
        *reinterpret_cast<__half2*>(Ch + (size_t)(row + 8) * Ntot + col) = __halves2half2(h2, h3);
        *reinterpret_cast<__half2*>(Cl + (size_t)(row + 8) * Ntot + col) = __halves2half2(l2, l3);
    }
}

// ---------------- plane-input GEMM (layers 2-3), exact R8 shape -----------
// CTA 128 x BN, 128 threads, warps 2x2, warp tile 64 x BN/2, 2-stage.
template<int BN, int ACT, int OUTF32>
__global__ void __launch_bounds__(128, 2)
gemm_p(const __half* __restrict__ Agh, const __half* __restrict__ Agl,
       const __half* __restrict__ Bgh, const __half* __restrict__ Bgl,
       const float* __restrict__ bias,
       __half* __restrict__ Ch, __half* __restrict__ Cl,
       float* __restrict__ Cf, int K, int Ntot)
{
    constexpr int NT   = BN / 16;
    constexpr int NP   = NT / 2;
    constexpr int AB   = 128 * RS * 2;
    constexpr int BB   = BN * RS * 2;
    constexpr int BUFB = 2 * AB + 2 * BB;
    extern __shared__ char smem[];
    const uint32_t sb = smem_u32(smem);

    const int tid = threadIdx.x;
    const int wid = tid >> 5, lane = tid & 31;
    const int wm  = wid >> 1, wn = wid & 1;
    const int g   = lane >> 2, tig = lane & 3;
    const int n0  = blockIdx.x * BN;
    const int m0  = blockIdx.y * 128;

    const uint32_t aoff = (uint32_t)((lane & 15) * RS + ((lane >> 4) << 3)) * 2;
    const uint32_t boff = (uint32_t)(((lane & 7) + ((lane >> 4) & 1) * 8) * RS
                                     + (((lane >> 3) & 1) << 3)) * 2;

    float acc[4][NT][4];
    #pragma unroll
    for (int i = 0; i < 4; i++)
        #pragma unroll
        for (int j = 0; j < NT; j++)
            #pragma unroll
            for (int q = 0; q < 4; q++) acc[i][j][q] = 0.0f;

    const int NC = K >> 5;

    auto cp_chunk = [&](int c, int b) {
        const int k0 = c << 5;
        const uint32_t a_h = sb + b * BUFB;
        const uint32_t a_l = a_h + AB;
        const uint32_t b_h = a_h + 2 * AB;
        const uint32_t b_l = b_h + BB;
        #pragma unroll
        for (int it = 0; it < 4; ++it) {
            int idx = tid + it * 128;
            int r = idx >> 2, kc = idx & 3;
            size_t so = (size_t)(m0 + r) * K + k0 + kc * 8;
            uint32_t doff = (uint32_t)(r * RS + kc * 8) * 2;
            cp16(a_h + doff, Agh + so);
            cp16(a_l + doff, Agl + so);
        }
        #pragma unroll
        for (int it = 0; it < BN / 32; ++it) {
            int idx = tid + it * 128;
            int r = idx >> 2, kc = idx & 3;
            size_t so = (size_t)(n0 + r) * K + k0 + kc * 8;
            uint32_t doff = (uint32_t)(r * RS + kc * 8) * 2;
            cp16(b_h + doff, Bgh + so);
            cp16(b_l + doff, Bgl + so);
        }
        cp_commit();
    };

    cp_chunk(0, 0);
    for (int c = 0; c < NC; ++c) {
        const int b = c & 1;
        if (c + 1 < NC) {
            cp_chunk(c + 1, b ^ 1);
            asm volatile("cp.async.wait_group 1;" ::: "memory");
        } else {
            asm volatile("cp.async.wait_group 0;" ::: "memory");
        }
        __syncthreads();

        const uint32_t base = sb + b * BUFB;
        const uint32_t sAh = base, sAl = base + AB;
        const uint32_t sBh = base + 2 * AB, sBl = sBh + BB;
        #pragma unroll
        for (int ks = 0; ks < 2; ++ks) {
            const uint32_t kb = (uint32_t)ks * 32;
            uint32_t ah[4][4], al[4][4], bh[NP][4], bl[NP][4];
            #pragma unroll
            for (int mt = 0; mt < 4; ++mt) {
                const uint32_t ro = (uint32_t)(wm * 64 + mt * 16) * (RS * 2);
                ldm_x4(ah[mt], sAh + ro + kb + aoff);
                ldm_x4(al[mt], sAl + ro + kb + aoff);
            }
            #pragma unroll
            for (int p = 0; p < NP; ++p) {
                const uint32_t no = (uint32_t)(wn * NT * 8 + p * 16) * (RS * 2);
                ldm_x4(bh[p], sBh + no + kb + boff);
                ldm_x4(bl[p], sBl + no + kb + boff);
            }
            #pragma unroll
            for (int mt = 0; mt < 4; ++mt)
                #pragma unroll
                for (int p = 0; p < NP; ++p) {
                    mma_f16(acc[mt][2*p],   ah[mt], &bh[p][0]);
                    mma_f16(acc[mt][2*p+1], ah[mt], &bh[p][2]);
                }
            #pragma unroll
            for (int mt = 0; mt < 4; ++mt)
                #pragma unroll
                for (int p = 0; p < NP; ++p) {
                    mma_f16(acc[mt][2*p],   al[mt], &bh[p][0]);
                    mma_f16(acc[mt][2*p+1], al[mt], &bh[p][2]);
                }
            #pragma unroll
            for (int mt = 0; mt < 4; ++mt)
                #pragma unroll
                for (int p = 0; p < NP; ++p) {
                    mma_f16(acc[mt][2*p],   ah[mt], &bl[p][0]);
                    mma_f16(acc[mt][2*p+1], ah[mt], &bl[p][2]);
                }
        }
        __syncthreads();
    }

    #pragma unroll
    for (int mt = 0; mt < 4; ++mt) {
        const int row = m0 + wm * 64 + mt * 16 + g;
        #pragma unroll
        for (int nt = 0; nt < NT; ++nt) {
            const int col = n0 + wn * (NT * 8) + nt * 8 + tig * 2;
            epi_store<ACT, OUTF32>(acc[mt][nt], row, col, Ntot, bias, Ch, Cl, Cf);
        }
    }
}

// ---------------- fp32-input GEMM (layer 1), exact R8 shape ---------------
__global__ void __launch_bounds__(128, 2)
gemm_x(const float* __restrict__ A, const __half* __restrict__ Bgh,
       const __half* __restrict__ Bgl, const float* __restrict__ bias,
       __half* __restrict__ Ch, __half* __restrict__ Cl, int K, int Ntot)
{
    constexpr int BN   = 128;
    constexpr int NT   = 8;
    constexpr int NP   = 4;
    constexpr int AB   = 128 * RS * 2;
    constexpr int BB   = BN * RS * 2;
    constexpr int BUFB = 2 * AB + 2 * BB;
    extern __shared__ char smem[];
    const uint32_t sb = smem_u32(smem);

    const int tid = threadIdx.x;
    const int wid = tid >> 5, lane = tid & 31;
    const int wm  = wid >> 1, wn = wid & 1;
    const int g   = lane >> 2, tig = lane & 3;
    const int n0  = blockIdx.x * BN;
    const int m0  = blockIdx.y * 128;

    const uint32_t aoff = (uint32_t)((lane & 15) * RS + ((lane >> 4) << 3)) * 2;
    const uint32_t boff = (uint32_t)(((lane & 7) + ((lane >> 4) & 1) * 8) * RS
                                     + (((lane >> 3) & 1) << 3)) * 2;

    float acc[4][NT][4];
    #pragma unroll
    for (int i = 0; i < 4; i++)
        #pragma unroll
        for (int j = 0; j < NT; j++)
            #pragma unroll
            for (int q = 0; q < 4; q++) acc[i][j][q] = 0.0f;

    const int NC  = K >> 5;
    const int ar  = tid >> 3;      // 0..15
    const int akq = tid & 7;

    float4 rA[8];

    auto cpB = [&](int c, int b) {
        const int k0 = c << 5;
        uint32_t dh = sb + b * BUFB + 2 * AB;
        uint32_t dl = dh + BB;
        #pragma unroll
        for (int it = 0; it < 4; ++it) {
            int idx = tid + it * 128;
            int n = idx >> 2, kc = idx & 3;
            size_t so = (size_t)(n0 + n) * K + k0 + kc * 8;
            uint32_t doff = (uint32_t)(n * RS + kc * 8) * 2;
            cp16(dh + doff, Bgh + so);
            cp16(dl + doff, Bgl + so);
        }
        cp_commit();
    };

    #pragma unroll
    for (int it = 0; it < 8; ++it)
        rA[it] = *reinterpret_cast<const float4*>(
            A + (size_t)(m0 + ar + it * 16) * K + akq * 4);
    cpB(0, 0);

    for (int c = 0; c < NC; ++c) {
        const int b = c & 1;
        if (c + 1 < NC) cpB(c + 1, b ^ 1);
        {
            __half* Ah = reinterpret_cast<__half*>(smem + b * BUFB);
            __half* Al = reinterpret_cast<__half*>(smem + b * BUFB + AB);
            #pragma unroll
            for (int it = 0; it < 8; ++it) {
                const int row = ar + it * 16;
                const float4 a = rA[it];
                __half hx = __float2half_rn(a.x), hy = __float2half_rn(a.y);
                __half hz = __float2half_rn(a.z), hw = __float2half_rn(a.w);
                __half lx = __float2half_rn(a.x - __half2float(hx));
                __half ly = __float2half_rn(a.y - __half2float(hy));
                __half lz = __float2half_rn(a.z - __half2float(hz));
                __half lw = __float2half_rn(a.w - __half2float(hw));
                *reinterpret_cast<uint2*>(Ah + row * RS + akq * 4) =
                    make_uint2(pack2(hx, hy), pack2(hz, hw));
                *reinterpret_cast<uint2*>(Al + row * RS + akq * 4) =
                    make_uint2(pack2(lx, ly), pack2(lz, lw));
            }
        }
        if (c + 1 < NC) {
            const float* An = A + (size_t)m0 * K + ((c + 1) << 5);
            #pragma unroll
            for (int it = 0; it < 8; ++it)
                rA[it] = *reinterpret_cast<const float4*>(
                    An + (size_t)(ar + it * 16) * K + akq * 4);
        }
        if (c + 1 < NC) asm volatile("cp.async.wait_group 1;" ::: "memory");
        else            asm volatile("cp.async.wait_group 0;" ::: "memory");
        __syncthreads();

        const uint32_t base = sb + b * BUFB;
        const uint32_t sAh = base, sAl = base + AB;
        const uint32_t sBh = base + 2 * AB, sBl = sBh + BB;
        #pragma unroll
        for (int ks = 0; ks < 2; ++ks) {
            const uint32_t kb = (uint32_t)ks * 32;
            uint32_t ah[4][4], al[4][4], bh[NP][4], bl[NP][4];
            #pragma unroll
            for (int mt = 0; mt < 4; ++mt) {
                const uint32_t ro = (uint32_t)(wm * 64 + mt * 16) * (RS * 2);
                ldm_x4(ah[mt], sAh + ro + kb + aoff);
                ldm_x4(al[mt], sAl + ro + kb + aoff);
            }
            #pragma unroll
            for (int p = 0; p < NP; ++p) {
                const uint32_t no = (uint32_t)(wn * NT * 8 + p * 16) * (RS * 2);
                ldm_x4(bh[p], sBh + no + kb + boff);
                ldm_x4(bl[p], sBl + no + kb + boff);
            }
            #pragma unroll
            for (int mt = 0; mt < 4; ++mt)
                #pragma unroll
                for (int p = 0; p < NP; ++p) {
                    mma_f16(acc[mt][2*p],   ah[mt], &bh[p][0]);
                    mma_f16(acc[mt][2*p+1], ah[mt], &bh[p][2]);
                }
            #pragma unroll
            for (int mt = 0; mt < 4; ++mt)
                #pragma unroll
                for (int p = 0; p < NP; ++p) {
                    mma_f16(acc[mt][2*p],   al[mt], &bh[p][0]);
                    mma_f16(acc[mt][2*p+1], al[mt], &bh[p][2]);
                }
            #pragma unroll
            for (int mt = 0; mt < 4; ++mt)
                #pragma unroll
                for (int p = 0; p < NP; ++p) {
                    mma_f16(acc[mt][2*p],   ah[mt], &bl[p][0]);
                    mma_f16(acc[mt][2*p+1], ah[mt], &bl[p][2]);
                }
        }
        __syncthreads();
    }

    #pragma unroll
    for (int mt = 0; mt < 4; ++mt) {
        const int row = m0 + wm * 64 + mt * 16 + g;
        #pragma unroll
        for (int nt = 0; nt < NT; ++nt) {
            const int col = n0 + wn * (NT * 8) + nt * 8 + tig * 2;
            epi_store<1, 0>(acc[mt][nt], row, col, Ntot, bias, Ch, Cl, nullptr);
        }
    }
}

// ---------------- fused detector: d2 = sig(sig(H3@D1+b1)@D2+b2) -----------
// CTA: 64(M) rows, 128 threads, warps 2x2. d1 never touches gmem.
// smem: region1 = 2-stage pipe bufs (61440B) -> later D2 weights;
//       region2 = d1 tile planes (40960B), chunked [4][64][RS] per plane.
__global__ void __launch_bounds__(128, 2)
gemm_det(const __half* __restrict__ Agh, const __half* __restrict__ Agl,
         const __half* __restrict__ W1h, const __half* __restrict__ W1l,
         const __half* __restrict__ W2h, const __half* __restrict__ W2l,
         const float* __restrict__ b1,  const float* __restrict__ b2,
         float* __restrict__ Cf)
{
    constexpr int AB   = 64 * RS * 2;       // 5120
    constexpr int BB   = 128 * RS * 2;      // 10240
    constexpr int BUFB = 2 * AB + 2 * BB;   // 30720
    constexpr int R2   = 2 * BUFB;          // 61440: d1 tile offset
    constexpr int PL   = 4 * 64 * RS;       // halves per plane in chunked tile (10240)
    extern __shared__ char smem[];
    const uint32_t sb = smem_u32(smem);

    const int tid = threadIdx.x;
    const int wid = tid >> 5, lane = tid & 31;
    const int wm  = wid >> 1, wn = wid & 1;
    const int g   = lane >> 2, tig = lane & 3;
    const int m0  = blockIdx.x * 64;

    const uint32_t aoff = (uint32_t)((lane & 15) * RS + ((lane >> 4) << 3)) * 2;
    const uint32_t boff = (uint32_t)(((lane & 7) + ((lane >> 4) & 1) * 8) * RS
                                     + (((lane >> 3) & 1) << 3)) * 2;

    // ================= Phase 1: D1 = sigmoid(H3 @ W1 + b1) ================
    // tile 64 x 128; warp tile 32 x 64 (mt 2, NT 8, NP 4)
    {
        float acc[2][8][4];
        #pragma unroll
        for (int i = 0; i < 2; i++)
            #pragma unroll
            for (int j = 0; j < 8; j++)
                #pragma unroll
                for (int q = 0; q < 4; q++) acc[i][j][q] = 0.0f;

        auto cp_chunk = [&](int c, int b) {
            const int k0 = c << 5;
            const uint32_t a_h = sb + b * BUFB;
            const uint32_t a_l = a_h + AB;
            const uint32_t b_h = a_h + 2 * AB;
            const uint32_t b_l = b_h + BB;
            #pragma unroll
            for (int it = 0; it < 2; ++it) {           // A: 64 rows x 4 kc
                int idx = tid + it * 128;
                int r = idx >> 2, kc = idx & 3;
                size_t so = (size_t)(m0 + r) * HD3 + k0 + kc * 8;
                uint32_t doff = (uint32_t)(r * RS + kc * 8) * 2;
                cp16(a_h + doff, Agh + so);
                cp16(a_l + doff, Agl + so);
            }
            #pragma unroll
            for (int it = 0; it < 4; ++it) {           // B: 128 rows x 4 kc
                int idx = tid + it * 128;
                int r = idx >> 2, kc = idx & 3;
                size_t so = (size_t)r * HD3 + k0 + kc * 8;
                uint32_t doff = (uint32_t)(r * RS + kc * 8) * 2;
                cp16(b_h + doff, W1h + so);
                cp16(b_l + doff, W1l + so);
            }
            cp_commit();
        };

        cp_chunk(0, 0);
        for (int c = 0; c < 4; ++c) {
            const int b = c & 1;
            if (c + 1 < 4) {
                cp_chunk(c + 1, b ^ 1);
                asm volatile("cp.async.wait_group 1;" ::: "memory");
            } else {
                asm volatile("cp.async.wait_group 0;" ::: "memory");
            }
            __syncthreads();

            const uint32_t base = sb + b * BUFB;
            const uint32_t sAh = base, sAl = base + AB;
            const uint32_t sBh = base + 2 * AB, sBl = sBh + BB;
            #pragma unroll
            for (int ks = 0; ks < 2; ++ks) {
                const uint32_t kb = (uint32_t)ks * 32;
                uint32_t ah[2][4], al[2][4], bh[4][4], bl[4][4];
                #pragma unroll
                for (int mt = 0; mt < 2; ++mt) {
                    const uint32_t ro = (uint32_t)(wm * 32 + mt * 16) * (RS * 2);
                    ldm_x4(ah[mt], sAh + ro + kb + aoff);
                    ldm_x4(al[mt], sAl + ro + kb + aoff);
                }
                #pragma unroll
                for (int p = 0; p < 4; ++p) {
                    const uint32_t no = (uint32_t)(wn * 64 + p * 16) * (RS * 2);
                    ldm_x4(bh[p], sBh + no + kb + boff);
                    ldm_x4(bl[p], sBl + no + kb + boff);
                }
                #pragma unroll
                for (int mt = 0; mt < 2; ++mt)
                    #pragma unroll
                    for (int p = 0; p < 4; ++p) {
                        mma_f16(acc[mt][2*p],   ah[mt], &bh[p][0]);
                        mma_f16(acc[mt][2*p+1], ah[mt], &bh[p][2]);
                    }
                #pragma unroll
                for (int mt = 0; mt < 2; ++mt)
                    #pragma unroll
                    for (int p = 0; p < 4; ++p) {
                        mma_f16(acc[mt][2*p],   al[mt], &bh[p][0]);
                        mma_f16(acc[mt][2*p+1], al[mt], &bh[p][2]);
                    }
                #pragma unroll
                for (int mt = 0; mt < 2; ++mt)
                    #pragma unroll
                    for (int p = 0; p < 4; ++p) {
                        mma_f16(acc[mt][2*p],   ah[mt], &bl[p][0]);
                        mma_f16(acc[mt][2*p+1], ah[mt], &bl[p][2]);
                    }
            }
            __syncthreads();
        }

        // epi: sigmoid -> smem d1 tile planes (chunked [4][64][RS])
        __half* d1h = reinterpret_cast<__half*>(smem + R2);
        __half* d1l = d1h + PL;
        #pragma unroll
        for (int mt = 0; mt < 2; ++mt) {
            const int row = wm * 32 + mt * 16 + g;       // 0..63
            #pragma unroll
            for (int nt = 0; nt < 8; ++nt) {
                const int col = wn * 64 + nt * 8 + tig * 2;   // 0..127
                const int chunk = col >> 5, kk = col & 31;
                const float bb0 = b1[col], bb1 = b1[col + 1];
                float v0 = 1.0f / (1.0f + expf(-(acc[mt][nt][0] + bb0)));
                float v1 = 1.0f / (1.0f + expf(-(acc[mt][nt][1] + bb1)));
                float v2 = 1.0f / (1.0f + expf(-(acc[mt][nt][2] + bb0)));
                float v3 = 1.0f / (1.0f + expf(-(acc[mt][nt][3] + bb1)));
                __half h0 = __float2half_rn(v0), h1 = __float2half_rn(v1);
                __half h2 = __float2half_rn(v2), h3 = __float2half_rn(v3);
                __half l0 = __float2half_rn(v0 - __half2float(h0));
                __half l1 = __float2half_rn(v1 - __half2float(h1));
                __half l2 = __float2half_rn(v2 - __half2float(h2));
                __half l3 = __float2half_rn(v3 - __half2float(h3));
                int o0 = (chunk * 64 + row) * RS + kk;
                int o1 = (chunk * 64 + row + 8) * RS + kk;
                *reinterpret_cast<__half2*>(d1h + o0) = __halves2half2(h0, h1);
                *reinterpret_cast<__half2*>(d1l + o0) = __halves2half2(l0, l1);
                *reinterpret_cast<__half2*>(d1h + o1) = __halves2half2(h2, h3);
                *reinterpret_cast<__half2*>(d1l + o1) = __halves2half2(l2, l3);
            }
        }
    }

    // ============ Phase 2: load D2 weights into region1 (pipe area) =======
    // layout chunked [4][64][RS] per plane; lo plane at +PL halves
    {
        #pragma unroll
        for (int it = 0; it < 8; ++it) {
            int idx = tid + it * 128;                  // 0..1023
            int r = idx >> 4;                          // 0..63 (n row)
            int kcg = idx & 15;                        // 16 groups of 8 halves (K=128)
            int chunk = kcg >> 2, kk = (kcg & 3) * 8;
            size_t so = (size_t)r * HD3 + kcg * 8;
            uint32_t dst = sb + (uint32_t)((chunk * 64 + r) * RS + kk) * 2;
            cp16(dst, W2h + so);
            cp16(dst + PL * 2, W2l + so);
        }
        cp_commit();
        asm volatile("cp.async.wait_group 0;" ::: "memory");
    }
    __syncthreads();

    // ================= Phase 3: D2 = sigmoid(d1 @ W2 + b2) ================
    // tile 64 x 64; warp tile 32 x 32 (mt 2, NT 4, NP 2)
    {
        float acc[2][4][4];
        #pragma unroll
        for (int i = 0; i < 2; i++)
            #pragma unroll
            for (int j = 0; j < 4; j++)
                #pragma unroll
                for (int q = 0; q < 4; q++) acc[i][j][q] = 0.0f;

        const uint32_t d1hb = sb + R2;
        const uint32_t d1lb = d1hb + PL * 2;
        const uint32_t w2hb = sb;
        const uint32_t w2lb = sb + PL * 2;

        #pragma unroll
        for (int c = 0; c < 4; ++c) {
            const uint32_t cb = (uint32_t)(c * 64 * RS) * 2;
            #pragma unroll
            for (int ks = 0; ks < 2; ++ks) {
                const uint32_t kb = (uint32_t)ks * 32;
                uint32_t ah[2][4], al[2][4], bh[2][4], bl[2][4];
                #pragma unroll
                for (int mt = 0; mt < 2; ++mt) {
                    const uint32_t ro = (uint32_t)(wm * 32 + mt * 16) * (RS * 2);
                    ldm_x4(ah[mt], d1hb + cb + ro + kb + aoff);
                    ldm_x4(al[mt], d1lb + cb + ro + kb + aoff);
                }
                #pragma unroll
                for (int p = 0; p < 2; ++p) {
                    const uint32_t no = (uint32_t)(wn * 32 + p * 16) * (RS * 2);
                    ldm_x4(bh[p], w2hb + cb + no + kb + boff);
                    ldm_x4(bl[p], w2lb + cb + no + kb + boff);
                }
                #pragma unroll
                for (int mt = 0; mt < 2; ++mt)
                    #pragma unroll
                    for (int p = 0; p < 2; ++p) {
                        mma_f16(acc[mt][2*p],   ah[mt], &bh[p][0]);
                        mma_f16(acc[mt][2*p+1], ah[mt], &bh[p][2]);
                        mma_f16(acc[mt][2*p],   al[mt], &bh[p][0]);
                        mma_f16(acc[mt][2*p+1], al[mt], &bh[p][2]);
                        mma_f16(acc[mt][2*p],   ah[mt], &bl[p][0]);
                        mma_f16(acc[mt][2*p+1], ah[mt], &bl[p][2]);
                    }
            }
        }

        // epi: sigmoid -> d2 fp32 gmem
        #pragma unroll
        for (int mt = 0; mt < 2; ++mt) {
            const int row = m0 + wm * 32 + mt * 16 + g;
            #pragma unroll
            for (int nt = 0; nt < 4; ++nt) {
                const int col = wn * 32 + nt * 8 + tig * 2;
                const float bb0 = b2[col], bb1 = b2[col + 1];
                float v0 = 1.0f / (1.0f + expf(-(acc[mt][nt][0] + bb0)));
                float v1 = 1.0f / (1.0f + expf(-(acc[mt][nt][1] + bb1)));
                float v2 = 1.0f / (1.0f + expf(-(acc[mt][nt][2] + bb0)));
                float v3 = 1.0f / (1.0f + expf(-(acc[mt][nt][3] + bb1)));
                *reinterpret_cast<float2*>(Cf + (size_t)row * DET2 + col) = make_float2(v0, v1);
                *reinterpret_cast<float2*>(Cf + (size_t)(row + 8) * DET2 + col) = make_float2(v2, v3);
            }
        }
    }
}

// ---------------- per-bag finish ----------------
__global__ void __launch_bounds__(128)
finish_kernel(const float* __restrict__ d2v, const float* __restrict__ D3,
              const float* __restrict__ db3, const float* __restrict__ m,
              const float* __restrict__ u,
              const __half* __restrict__ H3h, const __half* __restrict__ H3l,
              const float* __restrict__ E,   const float* __restrict__ eb,
              float* __restrict__ outw, float* __restrict__ outv)
{
    const int n   = blockIdx.x;
    const int tid = threadIdx.x;

    __shared__ float s_d2[CC][DET2 + 1];
    __shared__ float s_D3[DET2];
    __shared__ float s_z[CC];
    __shared__ float s_w2[CC];
    __shared__ float s_w[CC];
    __shared__ int   s_keep[CC];
    __shared__ float s_red[128];
    __shared__ float s_mx, s_sum;

    const float* d2b = d2v + (size_t)n * CC * DET2;
    for (int idx = tid; idx < CC * DET2; idx += 128)
        s_d2[idx >> 6][idx & 63] = d2b[idx];
    if (tid < DET2) s_D3[tid] = D3[tid];
    __syncthreads();

    if (tid < CC) {
        const int c = tid;
        float dd = db3[0];
        #pragma unroll
        for (int j = 0; j < DET2; j++) dd = fmaf(s_d2[c][j], s_D3[j], dd);
        float logit = m[(size_t)n * CC + c] * dd;
        float uu = u[(size_t)n * CC + c];
        float gn = -logf(-logf(uu));
        s_z[c] = (logit + gn) / TAU;
    }
    __syncthreads();

    if (tid == 0) {
        float mx = s_z[0];
        for (int c = 1; c < CC; c++) mx = fmaxf(mx, s_z[c]);
        s_mx = mx;
    }
    __syncthreads();
    if (tid < CC) s_w2[tid] = expf(s_z[tid] - s_mx);
    __syncthreads();
    if (tid == 0) {
        float s = 0.0f;
        for (int c = 0; c < CC; c++) s += s_w2[c];
        s_sum = s;
    }
    __syncthreads();
    if (tid < CC) s_w2[tid] = s_w2[tid] / s_sum;
    __syncthreads();

    if (tid < CC) {
        const int c = tid;
        const float v = s_w2[c];
        int rank = 0;
        for (int c2 = 0; c2 < CC; c2++) {
            float v2 = s_w2[c2];
            rank += (v2 < v) || (v2 == v && c2 < c);
        }
        s_keep[c] = (rank >= KDROP);
    }
    __syncthreads();

    if (tid == 0) {
        float mx = -INFINITY;
        for (int c = 0; c < CC; c++)
            if (s_keep[c]) mx = fmaxf(mx, s_w2[c]);
        s_mx = mx;
    }
    __syncthreads();
    if (tid < CC) s_red[tid] = s_keep[tid] ? expf(s_w2[tid] - s_mx) : 0.0f;
    __syncthreads();
    if (tid == 0) {
        float s = 0.0f;
        for (int c = 0; c < CC; c++) s += s_red[c];
        s_sum = s;
    }
    __syncthreads();
    if (tid < CC) {
        float wv = s_keep[tid] ? s_red[tid] / s_sum : 0.0f;
        s_w[tid] = wv;
        outw[(size_t)n * CC + tid] = wv;
    }
    __syncthreads();

    {
        const __half* hb = H3h + (size_t)n * CC * HD3;
        const __half* lb = H3l + (size_t)n * CC * HD3;
        float a = 0.0f;
        #pragma unroll 8
        for (int c = 0; c < CC; c++) {
            float h3 = __half2float(hb[(size_t)c * HD3 + tid]) +
                       __half2float(lb[(size_t)c * HD3 + tid]);
            a = fmaf(s_w[c], h3, a);
        }
        s_red[tid] = a * E[tid];
    }
    __syncthreads();
    for (int off = 64; off > 0; off >>= 1) {
        if (tid < off) s_red[tid] += s_red[tid + off];
        __syncthreads();
    }
    if (tid == 0) outv[n] = s_red[0] + eb[0];
}

// ---------------- launch ----------------
static inline int smem_bytes(int BN) {
    return 2 * (2 * 128 * RS * 2 + 2 * BN * RS * 2);
}
static inline int smem_det() {
    return 2 * (2 * 64 * RS * 2 + 2 * 128 * RS * 2) + 4 * 64 * RS * 2 * 2; // 61440 + 40960
}

extern "C" void kernel_launch(void* const* d_in, const int* in_sizes, int n_in,
                              void* d_out, int out_size)
{
    const float* x   = (const float*)d_in[0];
    const float* m   = (const float*)d_in[1];
    const float* u   = (const float*)d_in[2];
    const float* W1  = (const float*)d_in[3];
    const float* b1  = (const float*)d_in[4];
    const float* W2  = (const float*)d_in[5];
    const float* b2  = (const float*)d_in[6];
    const float* W3  = (const float*)d_in[7];
    const float* b3  = (const float*)d_in[8];
    const float* D1  = (const float*)d_in[9];
    const float* db1 = (const float*)d_in[10];
    const float* D2  = (const float*)d_in[11];
    const float* db2 = (const float*)d_in[12];
    const float* D3  = (const float*)d_in[13];
    const float* db3 = (const float*)d_in[14];
    const float* E   = (const float*)d_in[15];
    const float* eb  = (const float*)d_in[16];

    static __half *pHh = nullptr, *pHl, *pH2h, *pH2l, *pH3h, *pH3l, *pwh, *pwl;
    static float  *pd2, *pscr;
    if (!pHh) {
        cudaGetSymbolAddress((void**)&pHh,  g_Hh);
        cudaGetSymbolAddress((void**)&pHl,  g_Hl);
        cudaGetSymbolAddress((void**)&pH2h, g_H2h);
        cudaGetSymbolAddress((void**)&pH2l, g_H2l);
        cudaGetSymbolAddress((void**)&pH3h, g_H3h);
        cudaGetSymbolAddress((void**)&pH3l, g_H3l);
        cudaGetSymbolAddress((void**)&pd2,  g_d2);
        cudaGetSymbolAddress((void**)&pscr, g_scr);
        cudaGetSymbolAddress((void**)&pwh,  g_wh);
        cudaGetSymbolAddress((void**)&pwl,  g_wl);
        cudaFuncSetAttribute(gemm_x, cudaFuncAttributeMaxDynamicSharedMemorySize, smem_bytes(128));
        cudaFuncSetAttribute(gemm_p<128,1,0>, cudaFuncAttributeMaxDynamicSharedMemorySize, smem_bytes(128));
        cudaFuncSetAttribute(gemm_det, cudaFuncAttributeMaxDynamicSharedMemorySize, smem_det());
    }

    float* outw = (float*)d_out;
    float* outv;
    if (out_size >= MROWS + NB)      { outv = outw + MROWS; }
    else if (out_size == MROWS)      { outv = pscr; }
    else                             { outv = (float*)d_out; outw = pscr; }

    prep_all<<<PREP_END/256, 256>>>(W1, W2, W3, D1, D2, pwh, pwl);

    const int G = MROWS / 128;   // 1024 m-blocks
    // layer 1: x fp32, K=512, N=256 (2 n-blocks), relu -> H planes
    gemm_x<<<dim3(2, G), 128, smem_bytes(128)>>>(
        x, pwh + OFF_W1, pwl + OFF_W1, b1, pHh, pHl, IND, HD1);
    // layer 2: K=256, N=256 (2 n-blocks), relu -> H2 planes
    gemm_p<128,1,0><<<dim3(2, G), 128, smem_bytes(128)>>>(
        pHh, pHl, pwh + OFF_W2, pwl + OFF_W2, b2, pH2h, pH2l, nullptr, HD1, HD2);
    // layer 3: K=256, N=128, relu -> H3 planes
    gemm_p<128,1,0><<<dim3(1, G), 128, smem_bytes(128)>>>(
        pH2h, pH2l, pwh + OFF_W3, pwl + OFF_W3, b3, pH3h, pH3l, nullptr, HD2, HD3);
    // fused detector: H3 -> d1 (smem only) -> d2 fp32
    gemm_det<<<MROWS / 64, 128, smem_det()>>>(
        pH3h, pH3l, pwh + OFF_D1, pwl + OFF_D1,
        pwh + OFF_D2, pwl + OFF_D2, db1, db2, pd2);

    finish_kernel<<<NB, 128>>>(pd2, D3, db3, m, u, pH3h, pH3l, E, eb, outw, outv);
}